// round 8
// baseline (speedup 1.0000x reference)
#include <cuda_runtime.h>
#include <cuda_bf16.h>
#include <cstdint>
#include <math.h>

// out = gelu_exact(x @ w1) @ w2 per expert.
// Split-bf16 scheme on HMMA (mma.sync m16n8k16 bf16):
//   C = Ah*Bh + Al*Bh + Ah*Bl   (drop Al*Bl, ~2^-18 relative)

static constexpr int E = 8;
static constexpr int M = 2048;
static constexpr int D = 1024;
static constexpr int H = 4096;

// ---- device scratch (no runtime allocation allowed) ----
__device__ __align__(256) __nv_bfloat16 g_xh[(size_t)E * M * D];
__device__ __align__(256) __nv_bfloat16 g_xl[(size_t)E * M * D];
__device__ __align__(256) __nv_bfloat16 g_w1h[(size_t)E * H * D];  // [E][H][D] (transposed, K-major)
__device__ __align__(256) __nv_bfloat16 g_w1l[(size_t)E * H * D];
__device__ __align__(256) __nv_bfloat16 g_w2h[(size_t)E * D * H];  // [E][D][H] (transposed, K-major)
__device__ __align__(256) __nv_bfloat16 g_w2l[(size_t)E * D * H];
__device__ __align__(256) __nv_bfloat16 g_hh[(size_t)E * M * H];   // hidden hi [E][M][H]
__device__ __align__(256) __nv_bfloat16 g_hl[(size_t)E * M * H];   // hidden lo

// ======================= helpers =======================
__device__ __forceinline__ uint32_t smem_u32(const void* p) {
    uint32_t a;
    asm("{ .reg .u64 t; cvta.to.shared.u64 t, %1; cvt.u32.u64 %0, t; }" : "=r"(a) : "l"(p));
    return a;
}
__device__ __forceinline__ void cp16(uint32_t dst, const void* src) {
    asm volatile("cp.async.cg.shared.global [%0], [%1], 16;" :: "r"(dst), "l"(src));
}
#define CP_COMMIT() asm volatile("cp.async.commit_group;" ::: "memory")

__device__ __forceinline__ void ldsm_x4(uint32_t& r0, uint32_t& r1, uint32_t& r2,
                                        uint32_t& r3, uint32_t addr) {
    asm volatile("ldmatrix.sync.aligned.m8n8.x4.shared.b16 {%0,%1,%2,%3}, [%4];"
                 : "=r"(r0), "=r"(r1), "=r"(r2), "=r"(r3) : "r"(addr));
}
__device__ __forceinline__ void mma_bf16(float& d0, float& d1, float& d2, float& d3,
                                         uint32_t a0, uint32_t a1, uint32_t a2, uint32_t a3,
                                         uint32_t b0, uint32_t b1) {
    asm volatile(
        "mma.sync.aligned.m16n8k16.row.col.f32.bf16.bf16.f32 "
        "{%0,%1,%2,%3}, {%4,%5,%6,%7}, {%8,%9}, {%0,%1,%2,%3};"
        : "+f"(d0), "+f"(d1), "+f"(d2), "+f"(d3)
        : "r"(a0), "r"(a1), "r"(a2), "r"(a3), "r"(b0), "r"(b1));
}

__device__ __forceinline__ float gelu_exact(float x) {
    return 0.5f * x * (1.0f + erff(x * 0.7071067811865476f));
}

// ======================= conversion kernels =======================
__global__ void split_kernel(const float4* __restrict__ in,
                             __nv_bfloat16* __restrict__ hi,
                             __nv_bfloat16* __restrict__ lo) {
    size_t i = (size_t)blockIdx.x * blockDim.x + threadIdx.x;
    float4 v = in[i];
    float f[4] = {v.x, v.y, v.z, v.w};
    __nv_bfloat16 h[4], l[4];
#pragma unroll
    for (int j = 0; j < 4; j++) {
        h[j] = __float2bfloat16(f[j]);
        l[j] = __float2bfloat16(f[j] - __bfloat162float(h[j]));
    }
    *reinterpret_cast<uint2*>(hi + i * 4) = *reinterpret_cast<uint2*>(h);
    *reinterpret_cast<uint2*>(lo + i * 4) = *reinterpret_cast<uint2*>(l);
}

// in [R][C] per expert -> out [C][R] split to hi/lo
__global__ void transpose_split_kernel(const float* __restrict__ in,
                                       __nv_bfloat16* __restrict__ oh,
                                       __nv_bfloat16* __restrict__ ol,
                                       int R, int C) {
    __shared__ float tile[32][33];
    const float* src = in + (size_t)blockIdx.z * R * C;
    __nv_bfloat16* dh = oh + (size_t)blockIdx.z * R * C;
    __nv_bfloat16* dl = ol + (size_t)blockIdx.z * R * C;
    int c0 = blockIdx.x * 32, r0 = blockIdx.y * 32;
    int tx = threadIdx.x, ty = threadIdx.y;
#pragma unroll
    for (int i = ty; i < 32; i += 8)
        tile[i][tx] = src[(size_t)(r0 + i) * C + c0 + tx];
    __syncthreads();
#pragma unroll
    for (int i = ty; i < 32; i += 8) {
        float v = tile[tx][i];
        __nv_bfloat16 h = __float2bfloat16(v);
        float r = v - __bfloat162float(h);
        size_t o = (size_t)(c0 + i) * R + r0 + tx;
        dh[o] = h;
        dl[o] = __float2bfloat16(r);
    }
}

// ======================= HMMA GEMM =======================
// CTA tile 128x128, BK=32 bf16. 16 warps (4x4), warp tile 32x32.
// SMEM per stage: 4 planes (Ah, Al, Bh, Bl), each 128 rows x 80B (padded; 64B data).
// 80B row stride -> quad slot (5r + c) mod 8 distinct for r=0..7: conflict-free ldmatrix.
static constexpr int BK = 32;
static constexpr int ROWB = 80;                       // padded row stride
static constexpr int PLANE_BYTES = 128 * ROWB;        // 10240
static constexpr int STAGE_BYTES = 4 * PLANE_BYTES;   // 40960
static constexpr int STAGES = 4;
static constexpr int SMEM_BYTES = STAGES * STAGE_BYTES;  // 163840
static constexpr int AH_OFF = 0;
static constexpr int AL_OFF = PLANE_BYTES;
static constexpr int BH_OFF = 2 * PLANE_BYTES;
static constexpr int BL_OFF = 3 * PLANE_BYTES;

template <bool GELU_SPLIT>
__global__ __launch_bounds__(512, 1)
void hmma_gemm_kernel(const __nv_bfloat16* __restrict__ Ah,
                      const __nv_bfloat16* __restrict__ Al,
                      const __nv_bfloat16* __restrict__ Bh,
                      const __nv_bfloat16* __restrict__ Bl,
                      float* __restrict__ Cout,
                      __nv_bfloat16* __restrict__ Ch,
                      __nv_bfloat16* __restrict__ Cl,
                      int Mdim, int Ndim, int Kdim) {
    extern __shared__ char smem[];
    const uint32_t sb = smem_u32(smem);

    const int tid = threadIdx.x;
    const int wid = tid >> 5;
    const int lane = tid & 31;
    const int e = blockIdx.z;
    const int brow = blockIdx.y * 128;
    const int bcol = blockIdx.x * 128;

    const size_t mk = (size_t)Mdim * Kdim, nk = (size_t)Ndim * Kdim;
    const size_t mn = (size_t)Mdim * Ndim;
    Ah += (size_t)e * mk; Al += (size_t)e * mk;
    Bh += (size_t)e * nk; Bl += (size_t)e * nk;
    if (GELU_SPLIT) { Ch += (size_t)e * mn; Cl += (size_t)e * mn; }
    else            { Cout += (size_t)e * mn; }

    const int warp_m = (wid >> 2) * 32;   // 0,32,64,96
    const int warp_n = (wid & 3) * 32;    // 0,32,64,96

    // per-lane ldmatrix row/quad decomposition
    const int lr = lane & 7, lg = lane >> 3;
    const int a_row = lr + (lg & 1) * 8;     // row within 16-row tile
    const int a_q   = lg >> 1;               // k-half
    const int b_row = lr + (lg >> 1) * 8;    // row within 16-n-row pair
    const int b_q   = lg & 1;

    float acc[2][4][4];
#pragma unroll
    for (int i = 0; i < 2; i++)
#pragma unroll
        for (int j = 0; j < 4; j++)
#pragma unroll
            for (int r = 0; r < 4; r++) acc[i][j][r] = 0.0f;

    const int NK = Kdim / BK;

    auto load_stage = [&](int kc, int stage) {
        const int k0 = kc * BK;
        const uint32_t st = sb + stage * STAGE_BYTES;
        // 512 quads (16B) per plane; 512 threads -> 1 per plane
        const int r = tid >> 2, c = tid & 3;
        const uint32_t doff = r * ROWB + c * 16;
        const size_t aoff = (size_t)(brow + r) * Kdim + k0 + c * 8;
        const size_t boff = (size_t)(bcol + r) * Kdim + k0 + c * 8;
        cp16(st + AH_OFF + doff, Ah + aoff);
        cp16(st + AL_OFF + doff, Al + aoff);
        cp16(st + BH_OFF + doff, Bh + boff);
        cp16(st + BL_OFF + doff, Bl + boff);
        CP_COMMIT();
    };

    load_stage(0, 0);
    if (NK > 1) load_stage(1, 1);
    if (NK > 2) load_stage(2, 2);

    for (int k = 0; k < NK; k++) {
        const int s = k & (STAGES - 1);
        const uint32_t st = sb + s * STAGE_BYTES;
        const int rem = NK - 1 - k;
        if (rem >= 2)      asm volatile("cp.async.wait_group 2;" ::: "memory");
        else if (rem == 1) asm volatile("cp.async.wait_group 1;" ::: "memory");
        else               asm volatile("cp.async.wait_group 0;" ::: "memory");
        __syncthreads();

        // ---- hoist ALL fragment loads for this chunk (both ks halves) ----
        uint32_t ah[2][2][4], al[2][2][4], bh[2][4][2], bl[2][4][2];
#pragma unroll
        for (int ks = 0; ks < 2; ks++) {
            const uint32_t a_base =
                st + (warp_m + a_row) * ROWB + (2 * ks + a_q) * 16;
#pragma unroll
            for (int i = 0; i < 2; i++) {
                ldsm_x4(ah[ks][i][0], ah[ks][i][1], ah[ks][i][2], ah[ks][i][3],
                        a_base + AH_OFF + i * 16 * ROWB);
                ldsm_x4(al[ks][i][0], al[ks][i][1], al[ks][i][2], al[ks][i][3],
                        a_base + AL_OFF + i * 16 * ROWB);
            }
            const uint32_t b_base =
                st + (warp_n + b_row) * ROWB + (2 * ks + b_q) * 16;
#pragma unroll
            for (int jp = 0; jp < 2; jp++) {
                ldsm_x4(bh[ks][2 * jp][0], bh[ks][2 * jp][1],
                        bh[ks][2 * jp + 1][0], bh[ks][2 * jp + 1][1],
                        b_base + BH_OFF + jp * 16 * ROWB);
                ldsm_x4(bl[ks][2 * jp][0], bl[ks][2 * jp][1],
                        bl[ks][2 * jp + 1][0], bl[ks][2 * jp + 1][1],
                        b_base + BL_OFF + jp * 16 * ROWB);
            }
        }

        // prefetch next stage while fragments are in flight
        if (k + 3 < NK) load_stage(k + 3, (k + 3) & (STAGES - 1));

        // ---- 48 MMAs, plane-outer / ks-inner: same-acc gap = 16 MMAs ----
#pragma unroll
        for (int ks = 0; ks < 2; ks++)
#pragma unroll
            for (int i = 0; i < 2; i++)
#pragma unroll
                for (int j = 0; j < 4; j++)
                    mma_bf16(acc[i][j][0], acc[i][j][1], acc[i][j][2], acc[i][j][3],
                             ah[ks][i][0], ah[ks][i][1], ah[ks][i][2], ah[ks][i][3],
                             bh[ks][j][0], bh[ks][j][1]);
#pragma unroll
        for (int ks = 0; ks < 2; ks++)
#pragma unroll
            for (int i = 0; i < 2; i++)
#pragma unroll
                for (int j = 0; j < 4; j++)
                    mma_bf16(acc[i][j][0], acc[i][j][1], acc[i][j][2], acc[i][j][3],
                             al[ks][i][0], al[ks][i][1], al[ks][i][2], al[ks][i][3],
                             bh[ks][j][0], bh[ks][j][1]);
#pragma unroll
        for (int ks = 0; ks < 2; ks++)
#pragma unroll
            for (int i = 0; i < 2; i++)
#pragma unroll
                for (int j = 0; j < 4; j++)
                    mma_bf16(acc[i][j][0], acc[i][j][1], acc[i][j][2], acc[i][j][3],
                             ah[ks][i][0], ah[ks][i][1], ah[ks][i][2], ah[ks][i][3],
                             bl[ks][j][0], bl[ks][j][1]);
    }

    // ---- epilogue ----
    const int lrow = lane >> 2;          // 0..7
    const int lcol = (lane & 3) * 2;     // 0,2,4,6
#pragma unroll
    for (int i = 0; i < 2; i++) {
#pragma unroll
        for (int hh = 0; hh < 2; hh++) {
            const size_t row = (size_t)(brow + warp_m + i * 16 + lrow + hh * 8);
#pragma unroll
            for (int j = 0; j < 4; j++) {
                const size_t col = (size_t)(bcol + warp_n + j * 8 + lcol);
                float v0 = acc[i][j][2 * hh];
                float v1 = acc[i][j][2 * hh + 1];
                if (GELU_SPLIT) {
                    v0 = gelu_exact(v0);
                    v1 = gelu_exact(v1);
                    __nv_bfloat16 h0 = __float2bfloat16(v0);
                    __nv_bfloat16 h1 = __float2bfloat16(v1);
                    __nv_bfloat162 hp; hp.x = h0; hp.y = h1;
                    __nv_bfloat162 lp;
                    lp.x = __float2bfloat16(v0 - __bfloat162float(h0));
                    lp.y = __float2bfloat16(v1 - __bfloat162float(h1));
                    *reinterpret_cast<uint32_t*>(Ch + row * Ndim + col) =
                        *reinterpret_cast<uint32_t*>(&hp);
                    *reinterpret_cast<uint32_t*>(Cl + row * Ndim + col) =
                        *reinterpret_cast<uint32_t*>(&lp);
                } else {
                    float2 o; o.x = v0; o.y = v1;
                    *reinterpret_cast<float2*>(Cout + row * Ndim + col) = o;
                }
            }
        }
    }
}

// ======================= launch =======================
extern "C" void kernel_launch(void* const* d_in, const int* in_sizes, int n_in,
                              void* d_out, int out_size) {
    const float* x  = (const float*)d_in[0];
    const float* w1 = (const float*)d_in[1];
    const float* w2 = (const float*)d_in[2];
    float* out = (float*)d_out;
    (void)in_sizes; (void)n_in; (void)out_size;

    cudaFuncSetAttribute(hmma_gemm_kernel<true>,
                         cudaFuncAttributeMaxDynamicSharedMemorySize, SMEM_BYTES);
    cudaFuncSetAttribute(hmma_gemm_kernel<false>,
                         cudaFuncAttributeMaxDynamicSharedMemorySize, SMEM_BYTES);

    __nv_bfloat16 *xh, *xl, *w1h, *w1l, *w2h, *w2l, *hh, *hl;
    cudaGetSymbolAddress((void**)&xh,  g_xh);
    cudaGetSymbolAddress((void**)&xl,  g_xl);
    cudaGetSymbolAddress((void**)&w1h, g_w1h);
    cudaGetSymbolAddress((void**)&w1l, g_w1l);
    cudaGetSymbolAddress((void**)&w2h, g_w2h);
    cudaGetSymbolAddress((void**)&w2l, g_w2l);
    cudaGetSymbolAddress((void**)&hh,  g_hh);
    cudaGetSymbolAddress((void**)&hl,  g_hl);

    // 1) split x
    {
        size_t n4 = (size_t)E * M * D / 4;
        split_kernel<<<(unsigned)(n4 / 256), 256>>>((const float4*)x, xh, xl);
    }
    // 2) transpose+split w1: [E][D][H] -> [E][H][D]
    {
        dim3 grid(H / 32, D / 32, E), blk(32, 8);
        transpose_split_kernel<<<grid, blk>>>(w1, w1h, w1l, D, H);
    }
    // 3) transpose+split w2: [E][H][D] -> [E][D][H]
    {
        dim3 grid(D / 32, H / 32, E), blk(32, 8);
        transpose_split_kernel<<<grid, blk>>>(w2, w2h, w2l, H, D);
    }
    // 4) GEMM1 + GELU + split -> hidden planes  (M x H, K = D)
    {
        dim3 grid(H / 128, M / 128, E);
        hmma_gemm_kernel<true><<<grid, 512, SMEM_BYTES>>>(
            xh, xl, w1h, w1l, nullptr, hh, hl, M, H, D);
    }
    // 5) GEMM2 -> out  (M x D, K = H)
    {
        dim3 grid(D / 128, M / 128, E);
        hmma_gemm_kernel<false><<<grid, 512, SMEM_BYTES>>>(
            hh, hl, w2h, w2l, out, nullptr, nullptr, M, D, H);
    }
}

// round 9
// speedup vs baseline: 1.2865x; 1.2865x over previous
#include <cuda_runtime.h>
#include <cuda_bf16.h>
#include <cstdint>
#include <math.h>

// out = gelu_exact(x @ w1) @ w2 per expert.
// Split-bf16 scheme on HMMA (mma.sync m16n8k16 bf16):
//   C = Ah*Bh + Al*Bh + Ah*Bl   (drop Al*Bl, ~2^-18 relative)
// SMEM: 128B rows packing [hi 64B | lo 64B], SW128 XOR swizzle ->
// conflict-free cp.async stores AND conflict-free ldmatrix reads.

static constexpr int E = 8;
static constexpr int M = 2048;
static constexpr int D = 1024;
static constexpr int H = 4096;

// ---- device scratch (no runtime allocation allowed) ----
__device__ __align__(256) __nv_bfloat16 g_xh[(size_t)E * M * D];
__device__ __align__(256) __nv_bfloat16 g_xl[(size_t)E * M * D];
__device__ __align__(256) __nv_bfloat16 g_w1h[(size_t)E * H * D];  // [E][H][D] (transposed, K-major)
__device__ __align__(256) __nv_bfloat16 g_w1l[(size_t)E * H * D];
__device__ __align__(256) __nv_bfloat16 g_w2h[(size_t)E * D * H];  // [E][D][H] (transposed, K-major)
__device__ __align__(256) __nv_bfloat16 g_w2l[(size_t)E * D * H];
__device__ __align__(256) __nv_bfloat16 g_hh[(size_t)E * M * H];   // hidden hi [E][M][H]
__device__ __align__(256) __nv_bfloat16 g_hl[(size_t)E * M * H];   // hidden lo

// ======================= helpers =======================
__device__ __forceinline__ uint32_t smem_u32(const void* p) {
    uint32_t a;
    asm("{ .reg .u64 t; cvta.to.shared.u64 t, %1; cvt.u32.u64 %0, t; }" : "=r"(a) : "l"(p));
    return a;
}
__device__ __forceinline__ void cp16(uint32_t dst, const void* src) {
    asm volatile("cp.async.cg.shared.global [%0], [%1], 16;" :: "r"(dst), "l"(src));
}
#define CP_COMMIT() asm volatile("cp.async.commit_group;" ::: "memory")

__device__ __forceinline__ void ldsm_x4(uint32_t& r0, uint32_t& r1, uint32_t& r2,
                                        uint32_t& r3, uint32_t addr) {
    asm volatile("ldmatrix.sync.aligned.m8n8.x4.shared.b16 {%0,%1,%2,%3}, [%4];"
                 : "=r"(r0), "=r"(r1), "=r"(r2), "=r"(r3) : "r"(addr));
}
__device__ __forceinline__ void mma_bf16(float& d0, float& d1, float& d2, float& d3,
                                         uint32_t a0, uint32_t a1, uint32_t a2, uint32_t a3,
                                         uint32_t b0, uint32_t b1) {
    asm volatile(
        "mma.sync.aligned.m16n8k16.row.col.f32.bf16.bf16.f32 "
        "{%0,%1,%2,%3}, {%4,%5,%6,%7}, {%8,%9}, {%0,%1,%2,%3};"
        : "+f"(d0), "+f"(d1), "+f"(d2), "+f"(d3)
        : "r"(a0), "r"(a1), "r"(a2), "r"(a3), "r"(b0), "r"(b1));
}

// SW128 swizzle: XOR quad column (bits 6:4) with row mod 8 (bits 9:7)
__device__ __forceinline__ uint32_t swz(uint32_t off) { return off ^ ((off >> 3) & 0x70); }

__device__ __forceinline__ float gelu_exact(float x) {
    return 0.5f * x * (1.0f + erff(x * 0.7071067811865476f));
}

// ======================= conversion kernels =======================
__global__ void split_kernel(const float4* __restrict__ in,
                             __nv_bfloat16* __restrict__ hi,
                             __nv_bfloat16* __restrict__ lo) {
    size_t i = (size_t)blockIdx.x * blockDim.x + threadIdx.x;
    float4 v = in[i];
    float f[4] = {v.x, v.y, v.z, v.w};
    __nv_bfloat16 h[4], l[4];
#pragma unroll
    for (int j = 0; j < 4; j++) {
        h[j] = __float2bfloat16(f[j]);
        l[j] = __float2bfloat16(f[j] - __bfloat162float(h[j]));
    }
    *reinterpret_cast<uint2*>(hi + i * 4) = *reinterpret_cast<uint2*>(h);
    *reinterpret_cast<uint2*>(lo + i * 4) = *reinterpret_cast<uint2*>(l);
}

// in [R][C] per expert -> out [C][R] split to hi/lo
__global__ void transpose_split_kernel(const float* __restrict__ in,
                                       __nv_bfloat16* __restrict__ oh,
                                       __nv_bfloat16* __restrict__ ol,
                                       int R, int C) {
    __shared__ float tile[32][33];
    const float* src = in + (size_t)blockIdx.z * R * C;
    __nv_bfloat16* dh = oh + (size_t)blockIdx.z * R * C;
    __nv_bfloat16* dl = ol + (size_t)blockIdx.z * R * C;
    int c0 = blockIdx.x * 32, r0 = blockIdx.y * 32;
    int tx = threadIdx.x, ty = threadIdx.y;
#pragma unroll
    for (int i = ty; i < 32; i += 8)
        tile[i][tx] = src[(size_t)(r0 + i) * C + c0 + tx];
    __syncthreads();
#pragma unroll
    for (int i = ty; i < 32; i += 8) {
        float v = tile[tx][i];
        __nv_bfloat16 h = __float2bfloat16(v);
        float r = v - __bfloat162float(h);
        size_t o = (size_t)(c0 + i) * R + r0 + tx;
        dh[o] = h;
        dl[o] = __float2bfloat16(r);
    }
}

// ======================= HMMA GEMM =======================
// CTA tile 128x128, BK=32 bf16. 16 warps (4x4), warp tile 32x32.
// SMEM per stage: A tile (128 rows x [Ah|Al] 128B), B tile (128 rows x [Bh|Bl] 128B).
// Quads 0-3 of a row = hi plane (32 bf16), quads 4-7 = lo plane. SW128 swizzled.
static constexpr int BK = 32;
static constexpr int TILE_BYTES = 128 * 128;             // 16384 per A or B tile
static constexpr int B_OFF = TILE_BYTES;
static constexpr int STAGE_BYTES = 2 * TILE_BYTES;       // 32768
static constexpr int STAGES = 4;
static constexpr int SMEM_BYTES = STAGES * STAGE_BYTES;  // 131072

template <bool GELU_SPLIT>
__global__ __launch_bounds__(512, 1)
void hmma_gemm_kernel(const __nv_bfloat16* __restrict__ Ah,
                      const __nv_bfloat16* __restrict__ Al,
                      const __nv_bfloat16* __restrict__ Bh,
                      const __nv_bfloat16* __restrict__ Bl,
                      float* __restrict__ Cout,
                      __nv_bfloat16* __restrict__ Ch,
                      __nv_bfloat16* __restrict__ Cl,
                      int Mdim, int Ndim, int Kdim) {
    extern __shared__ char smem[];
    const uint32_t sb = smem_u32(smem);

    const int tid = threadIdx.x;
    const int wid = tid >> 5;
    const int lane = tid & 31;
    const int e = blockIdx.z;
    const int brow = blockIdx.y * 128;
    const int bcol = blockIdx.x * 128;

    const size_t mk = (size_t)Mdim * Kdim, nk = (size_t)Ndim * Kdim;
    const size_t mn = (size_t)Mdim * Ndim;
    Ah += (size_t)e * mk; Al += (size_t)e * mk;
    Bh += (size_t)e * nk; Bl += (size_t)e * nk;
    if (GELU_SPLIT) { Ch += (size_t)e * mn; Cl += (size_t)e * mn; }
    else            { Cout += (size_t)e * mn; }

    const int warp_m = (wid >> 2) * 32;   // 0,32,64,96
    const int warp_n = (wid & 3) * 32;    // 0,32,64,96

    // per-lane ldmatrix row/quad decomposition
    const int lr = lane & 7, lg = lane >> 3;
    const int a_row = lr + (lg & 1) * 8;     // row within 16-row tile
    const int a_q   = lg >> 1;               // k-half quad
    const int b_row = lr + (lg >> 1) * 8;    // row within 16-n-row pair
    const int b_q   = lg & 1;

    float acc[2][4][4];
#pragma unroll
    for (int i = 0; i < 2; i++)
#pragma unroll
        for (int j = 0; j < 4; j++)
#pragma unroll
            for (int r = 0; r < 4; r++) acc[i][j][r] = 0.0f;

    const int NK = Kdim / BK;

    // write decomposition: quad index qi -> row r = qi>>3, quad col c = qi&7
    // c<4: hi plane quad c ; c>=4: lo plane quad c-4. Swizzled dst.
    auto load_stage = [&](int kc, int stage) {
        const int k0 = kc * BK;
        const uint32_t st = sb + stage * STAGE_BYTES;
#pragma unroll
        for (int half = 0; half < 2; half++) {
            const int qi = tid + half * 512;
            const int r = qi >> 3, c = qi & 7;
            const uint32_t doff = swz(r * 128 + c * 16);
            const int csel = (c & 3) * 8;
            const __nv_bfloat16* sa = (c < 4 ? Ah : Al) + (size_t)(brow + r) * Kdim + k0 + csel;
            const __nv_bfloat16* sbp = (c < 4 ? Bh : Bl) + (size_t)(bcol + r) * Kdim + k0 + csel;
            cp16(st + doff, sa);
            cp16(st + B_OFF + doff, sbp);
        }
        CP_COMMIT();
    };

    load_stage(0, 0);
    if (NK > 1) load_stage(1, 1);
    if (NK > 2) load_stage(2, 2);

    for (int k = 0; k < NK; k++) {
        const int s = k & (STAGES - 1);
        const uint32_t st = sb + s * STAGE_BYTES;
        const int rem = NK - 1 - k;
        if (rem >= 2)      asm volatile("cp.async.wait_group 2;" ::: "memory");
        else if (rem == 1) asm volatile("cp.async.wait_group 1;" ::: "memory");
        else               asm volatile("cp.async.wait_group 0;" ::: "memory");
        __syncthreads();

#pragma unroll
        for (int ks = 0; ks < 2; ks++) {
            uint32_t ah[2][4], al[2][4], bh[4][2], bl[4][2];
            const int aq_h = 2 * ks + a_q;        // hi quad col (0..3)
            const int bq_h = 2 * ks + b_q;
#pragma unroll
            for (int i = 0; i < 2; i++) {
                const uint32_t arow_off = (warp_m + a_row + i * 16) * 128;
                ldsm_x4(ah[i][0], ah[i][1], ah[i][2], ah[i][3],
                        st + swz(arow_off + aq_h * 16));
                ldsm_x4(al[i][0], al[i][1], al[i][2], al[i][3],
                        st + swz(arow_off + (aq_h + 4) * 16));
            }
#pragma unroll
            for (int jp = 0; jp < 2; jp++) {
                const uint32_t brow_off = (warp_n + b_row + jp * 16) * 128;
                ldsm_x4(bh[2 * jp][0], bh[2 * jp][1], bh[2 * jp + 1][0], bh[2 * jp + 1][1],
                        st + B_OFF + swz(brow_off + bq_h * 16));
                ldsm_x4(bl[2 * jp][0], bl[2 * jp][1], bl[2 * jp + 1][0], bl[2 * jp + 1][1],
                        st + B_OFF + swz(brow_off + (bq_h + 4) * 16));
            }
            // plane-outer ordering: 8 independent acc chains between dependent MMAs
#pragma unroll
            for (int i = 0; i < 2; i++)
#pragma unroll
                for (int j = 0; j < 4; j++)
                    mma_bf16(acc[i][j][0], acc[i][j][1], acc[i][j][2], acc[i][j][3],
                             ah[i][0], ah[i][1], ah[i][2], ah[i][3], bh[j][0], bh[j][1]);
#pragma unroll
            for (int i = 0; i < 2; i++)
#pragma unroll
                for (int j = 0; j < 4; j++)
                    mma_bf16(acc[i][j][0], acc[i][j][1], acc[i][j][2], acc[i][j][3],
                             al[i][0], al[i][1], al[i][2], al[i][3], bh[j][0], bh[j][1]);
#pragma unroll
            for (int i = 0; i < 2; i++)
#pragma unroll
                for (int j = 0; j < 4; j++)
                    mma_bf16(acc[i][j][0], acc[i][j][1], acc[i][j][2], acc[i][j][3],
                             ah[i][0], ah[i][1], ah[i][2], ah[i][3], bl[j][0], bl[j][1]);
        }
        if (k + 3 < NK) load_stage(k + 3, (k + 3) & (STAGES - 1));
    }

    // ---- epilogue ----
    const int lrow = lane >> 2;          // 0..7
    const int lcol = (lane & 3) * 2;     // 0,2,4,6
#pragma unroll
    for (int i = 0; i < 2; i++) {
#pragma unroll
        for (int hh = 0; hh < 2; hh++) {
            const size_t row = (size_t)(brow + warp_m + i * 16 + lrow + hh * 8);
#pragma unroll
            for (int j = 0; j < 4; j++) {
                const size_t col = (size_t)(bcol + warp_n + j * 8 + lcol);
                float v0 = acc[i][j][2 * hh];
                float v1 = acc[i][j][2 * hh + 1];
                if (GELU_SPLIT) {
                    v0 = gelu_exact(v0);
                    v1 = gelu_exact(v1);
                    __nv_bfloat16 h0 = __float2bfloat16(v0);
                    __nv_bfloat16 h1 = __float2bfloat16(v1);
                    __nv_bfloat162 hp; hp.x = h0; hp.y = h1;
                    __nv_bfloat162 lp;
                    lp.x = __float2bfloat16(v0 - __bfloat162float(h0));
                    lp.y = __float2bfloat16(v1 - __bfloat162float(h1));
                    *reinterpret_cast<uint32_t*>(Ch + row * Ndim + col) =
                        *reinterpret_cast<uint32_t*>(&hp);
                    *reinterpret_cast<uint32_t*>(Cl + row * Ndim + col) =
                        *reinterpret_cast<uint32_t*>(&lp);
                } else {
                    float2 o; o.x = v0; o.y = v1;
                    *reinterpret_cast<float2*>(Cout + row * Ndim + col) = o;
                }
            }
        }
    }
}

// ======================= launch =======================
extern "C" void kernel_launch(void* const* d_in, const int* in_sizes, int n_in,
                              void* d_out, int out_size) {
    const float* x  = (const float*)d_in[0];
    const float* w1 = (const float*)d_in[1];
    const float* w2 = (const float*)d_in[2];
    float* out = (float*)d_out;
    (void)in_sizes; (void)n_in; (void)out_size;

    cudaFuncSetAttribute(hmma_gemm_kernel<true>,
                         cudaFuncAttributeMaxDynamicSharedMemorySize, SMEM_BYTES);
    cudaFuncSetAttribute(hmma_gemm_kernel<false>,
                         cudaFuncAttributeMaxDynamicSharedMemorySize, SMEM_BYTES);

    __nv_bfloat16 *xh, *xl, *w1h, *w1l, *w2h, *w2l, *hh, *hl;
    cudaGetSymbolAddress((void**)&xh,  g_xh);
    cudaGetSymbolAddress((void**)&xl,  g_xl);
    cudaGetSymbolAddress((void**)&w1h, g_w1h);
    cudaGetSymbolAddress((void**)&w1l, g_w1l);
    cudaGetSymbolAddress((void**)&w2h, g_w2h);
    cudaGetSymbolAddress((void**)&w2l, g_w2l);
    cudaGetSymbolAddress((void**)&hh,  g_hh);
    cudaGetSymbolAddress((void**)&hl,  g_hl);

    // 1) split x
    {
        size_t n4 = (size_t)E * M * D / 4;
        split_kernel<<<(unsigned)(n4 / 256), 256>>>((const float4*)x, xh, xl);
    }
    // 2) transpose+split w1: [E][D][H] -> [E][H][D]
    {
        dim3 grid(H / 32, D / 32, E), blk(32, 8);
        transpose_split_kernel<<<grid, blk>>>(w1, w1h, w1l, D, H);
    }
    // 3) transpose+split w2: [E][H][D] -> [E][D][H]
    {
        dim3 grid(D / 32, H / 32, E), blk(32, 8);
        transpose_split_kernel<<<grid, blk>>>(w2, w2h, w2l, H, D);
    }
    // 4) GEMM1 + GELU + split -> hidden planes  (M x H, K = D)
    {
        dim3 grid(H / 128, M / 128, E);
        hmma_gemm_kernel<true><<<grid, 512, SMEM_BYTES>>>(
            xh, xl, w1h, w1l, nullptr, hh, hl, M, H, D);
    }
    // 5) GEMM2 -> out  (M x D, K = H)
    {
        dim3 grid(D / 128, M / 128, E);
        hmma_gemm_kernel<false><<<grid, 512, SMEM_BYTES>>>(
            hh, hl, w2h, w2l, out, nullptr, nullptr, M, D, H);
    }
}

// round 10
// speedup vs baseline: 1.3245x; 1.0296x over previous
#include <cuda_runtime.h>
#include <cuda_bf16.h>
#include <cstdint>
#include <math.h>

// out = gelu_exact(x @ w1) @ w2 per expert.
// Split-bf16 scheme on HMMA (mma.sync m16n8k16 bf16):
//   C = Ah*Bh + Al*Bh + Ah*Bl   (drop Al*Bl, ~2^-18 relative)
// SMEM: 128B rows packing [hi 64B | lo 64B], SW128 XOR swizzle.
// 128x64 CTA tile, 256 threads -> 2 CTAs/SM so barrier bubbles interleave.

static constexpr int E = 8;
static constexpr int M = 2048;
static constexpr int D = 1024;
static constexpr int H = 4096;

// ---- device scratch (no runtime allocation allowed) ----
__device__ __align__(256) __nv_bfloat16 g_xh[(size_t)E * M * D];
__device__ __align__(256) __nv_bfloat16 g_xl[(size_t)E * M * D];
__device__ __align__(256) __nv_bfloat16 g_w1h[(size_t)E * H * D];  // [E][H][D] (transposed, K-major)
__device__ __align__(256) __nv_bfloat16 g_w1l[(size_t)E * H * D];
__device__ __align__(256) __nv_bfloat16 g_w2h[(size_t)E * D * H];  // [E][D][H] (transposed, K-major)
__device__ __align__(256) __nv_bfloat16 g_w2l[(size_t)E * D * H];
__device__ __align__(256) __nv_bfloat16 g_hh[(size_t)E * M * H];   // hidden hi [E][M][H]
__device__ __align__(256) __nv_bfloat16 g_hl[(size_t)E * M * H];   // hidden lo

// ======================= helpers =======================
__device__ __forceinline__ uint32_t smem_u32(const void* p) {
    uint32_t a;
    asm("{ .reg .u64 t; cvta.to.shared.u64 t, %1; cvt.u32.u64 %0, t; }" : "=r"(a) : "l"(p));
    return a;
}
__device__ __forceinline__ void cp16(uint32_t dst, const void* src) {
    asm volatile("cp.async.cg.shared.global [%0], [%1], 16;" :: "r"(dst), "l"(src));
}
#define CP_COMMIT() asm volatile("cp.async.commit_group;" ::: "memory")

__device__ __forceinline__ void ldsm_x4(uint32_t& r0, uint32_t& r1, uint32_t& r2,
                                        uint32_t& r3, uint32_t addr) {
    asm volatile("ldmatrix.sync.aligned.m8n8.x4.shared.b16 {%0,%1,%2,%3}, [%4];"
                 : "=r"(r0), "=r"(r1), "=r"(r2), "=r"(r3) : "r"(addr));
}
__device__ __forceinline__ void mma_bf16(float& d0, float& d1, float& d2, float& d3,
                                         uint32_t a0, uint32_t a1, uint32_t a2, uint32_t a3,
                                         uint32_t b0, uint32_t b1) {
    asm volatile(
        "mma.sync.aligned.m16n8k16.row.col.f32.bf16.bf16.f32 "
        "{%0,%1,%2,%3}, {%4,%5,%6,%7}, {%8,%9}, {%0,%1,%2,%3};"
        : "+f"(d0), "+f"(d1), "+f"(d2), "+f"(d3)
        : "r"(a0), "r"(a1), "r"(a2), "r"(a3), "r"(b0), "r"(b1));
}

// SW128 swizzle: XOR quad column (bits 6:4) with row mod 8 (bits 9:7)
__device__ __forceinline__ uint32_t swz(uint32_t off) { return off ^ ((off >> 3) & 0x70); }

__device__ __forceinline__ float gelu_exact(float x) {
    return 0.5f * x * (1.0f + erff(x * 0.7071067811865476f));
}

// ======================= conversion kernels =======================
__global__ void split_kernel(const float4* __restrict__ in,
                             __nv_bfloat16* __restrict__ hi,
                             __nv_bfloat16* __restrict__ lo) {
    size_t i = (size_t)blockIdx.x * blockDim.x + threadIdx.x;
    float4 v = in[i];
    float f[4] = {v.x, v.y, v.z, v.w};
    __nv_bfloat16 h[4], l[4];
#pragma unroll
    for (int j = 0; j < 4; j++) {
        h[j] = __float2bfloat16(f[j]);
        l[j] = __float2bfloat16(f[j] - __bfloat162float(h[j]));
    }
    *reinterpret_cast<uint2*>(hi + i * 4) = *reinterpret_cast<uint2*>(h);
    *reinterpret_cast<uint2*>(lo + i * 4) = *reinterpret_cast<uint2*>(l);
}

// in [R][C] per expert -> out [C][R] split to hi/lo
__global__ void transpose_split_kernel(const float* __restrict__ in,
                                       __nv_bfloat16* __restrict__ oh,
                                       __nv_bfloat16* __restrict__ ol,
                                       int R, int C) {
    __shared__ float tile[32][33];
    const float* src = in + (size_t)blockIdx.z * R * C;
    __nv_bfloat16* dh = oh + (size_t)blockIdx.z * R * C;
    __nv_bfloat16* dl = ol + (size_t)blockIdx.z * R * C;
    int c0 = blockIdx.x * 32, r0 = blockIdx.y * 32;
    int tx = threadIdx.x, ty = threadIdx.y;
#pragma unroll
    for (int i = ty; i < 32; i += 8)
        tile[i][tx] = src[(size_t)(r0 + i) * C + c0 + tx];
    __syncthreads();
#pragma unroll
    for (int i = ty; i < 32; i += 8) {
        float v = tile[tx][i];
        __nv_bfloat16 h = __float2bfloat16(v);
        float r = v - __bfloat162float(h);
        size_t o = (size_t)(c0 + i) * R + r0 + tx;
        dh[o] = h;
        dl[o] = __float2bfloat16(r);
    }
}

// ======================= HMMA GEMM =======================
// CTA tile 128x64, BK=32 bf16. 8 warps (4x2), warp tile 32x32. 2 CTAs/SM.
// SMEM per stage: A tile (128 rows x [Ah|Al] 128B) = 16KB, B tile (64 rows x 128B) = 8KB.
// Quads 0-3 of a row = hi plane (32 bf16), quads 4-7 = lo plane. SW128 swizzled.
static constexpr int BK = 32;
static constexpr int A_TILE_BYTES = 128 * 128;           // 16384
static constexpr int B_TILE_BYTES = 64 * 128;            // 8192
static constexpr int B_OFF = A_TILE_BYTES;
static constexpr int STAGE_BYTES = A_TILE_BYTES + B_TILE_BYTES;  // 24576
static constexpr int STAGES = 3;
static constexpr int SMEM_BYTES = STAGES * STAGE_BYTES;  // 73728

template <bool GELU_SPLIT>
__global__ __launch_bounds__(256, 2)
void hmma_gemm_kernel(const __nv_bfloat16* __restrict__ Ah,
                      const __nv_bfloat16* __restrict__ Al,
                      const __nv_bfloat16* __restrict__ Bh,
                      const __nv_bfloat16* __restrict__ Bl,
                      float* __restrict__ Cout,
                      __nv_bfloat16* __restrict__ Ch,
                      __nv_bfloat16* __restrict__ Cl,
                      int Mdim, int Ndim, int Kdim) {
    extern __shared__ char smem[];
    const uint32_t sb = smem_u32(smem);

    const int tid = threadIdx.x;
    const int wid = tid >> 5;
    const int lane = tid & 31;
    const int e = blockIdx.z;
    const int brow = blockIdx.y * 128;
    const int bcol = blockIdx.x * 64;

    const size_t mk = (size_t)Mdim * Kdim, nk = (size_t)Ndim * Kdim;
    const size_t mn = (size_t)Mdim * Ndim;
    Ah += (size_t)e * mk; Al += (size_t)e * mk;
    Bh += (size_t)e * nk; Bl += (size_t)e * nk;
    if (GELU_SPLIT) { Ch += (size_t)e * mn; Cl += (size_t)e * mn; }
    else            { Cout += (size_t)e * mn; }

    const int warp_m = (wid >> 1) * 32;   // 0,32,64,96
    const int warp_n = (wid & 1) * 32;    // 0,32

    // per-lane ldmatrix row/quad decomposition
    const int lr = lane & 7, lg = lane >> 3;
    const int a_row = lr + (lg & 1) * 8;     // row within 16-row tile
    const int a_q   = lg >> 1;               // k-half quad
    const int b_row = lr + (lg >> 1) * 8;    // row within 16-n-row pair
    const int b_q   = lg & 1;

    float acc[2][4][4];
#pragma unroll
    for (int i = 0; i < 2; i++)
#pragma unroll
        for (int j = 0; j < 4; j++)
#pragma unroll
            for (int r = 0; r < 4; r++) acc[i][j][r] = 0.0f;

    const int NK = Kdim / BK;

    // 1536 quads/stage (A: 1024, B: 512); 256 threads -> 6 cp16 each.
    auto load_stage = [&](int kc, int stage) {
        const int k0 = kc * BK;
        const uint32_t st = sb + stage * STAGE_BYTES;
#pragma unroll
        for (int p = 0; p < 4; p++) {   // A: 1024 quads
            const int qi = tid + p * 256;
            const int r = qi >> 3, c = qi & 7;
            const int csel = (c & 3) * 8;
            cp16(st + swz(r * 128 + c * 16),
                 (c < 4 ? Ah : Al) + (size_t)(brow + r) * Kdim + k0 + csel);
        }
#pragma unroll
        for (int p = 0; p < 2; p++) {   // B: 512 quads
            const int qi = tid + p * 256;
            const int r = qi >> 3, c = qi & 7;
            const int csel = (c & 3) * 8;
            cp16(st + B_OFF + swz(r * 128 + c * 16),
                 (c < 4 ? Bh : Bl) + (size_t)(bcol + r) * Kdim + k0 + csel);
        }
        CP_COMMIT();
    };

    load_stage(0, 0);
    if (NK > 1) load_stage(1, 1);

    int s = 0;
    for (int k = 0; k < NK; k++) {
        const uint32_t st = sb + s * STAGE_BYTES;
        if (k + 1 < NK) asm volatile("cp.async.wait_group 1;" ::: "memory");
        else            asm volatile("cp.async.wait_group 0;" ::: "memory");
        __syncthreads();

#pragma unroll
        for (int ks = 0; ks < 2; ks++) {
            uint32_t ah[2][4], al[2][4], bh[4][2], bl[4][2];
            const int aq_h = 2 * ks + a_q;        // hi quad col (0..3)
            const int bq_h = 2 * ks + b_q;
#pragma unroll
            for (int i = 0; i < 2; i++) {
                const uint32_t arow_off = (warp_m + a_row + i * 16) * 128;
                ldsm_x4(ah[i][0], ah[i][1], ah[i][2], ah[i][3],
                        st + swz(arow_off + aq_h * 16));
                ldsm_x4(al[i][0], al[i][1], al[i][2], al[i][3],
                        st + swz(arow_off + (aq_h + 4) * 16));
            }
#pragma unroll
            for (int jp = 0; jp < 2; jp++) {
                const uint32_t brow_off = (warp_n + b_row + jp * 16) * 128;
                ldsm_x4(bh[2 * jp][0], bh[2 * jp][1], bh[2 * jp + 1][0], bh[2 * jp + 1][1],
                        st + B_OFF + swz(brow_off + bq_h * 16));
                ldsm_x4(bl[2 * jp][0], bl[2 * jp][1], bl[2 * jp + 1][0], bl[2 * jp + 1][1],
                        st + B_OFF + swz(brow_off + (bq_h + 4) * 16));
            }
            // plane-outer ordering: 8 independent acc chains between dependent MMAs
#pragma unroll
            for (int i = 0; i < 2; i++)
#pragma unroll
                for (int j = 0; j < 4; j++)
                    mma_bf16(acc[i][j][0], acc[i][j][1], acc[i][j][2], acc[i][j][3],
                             ah[i][0], ah[i][1], ah[i][2], ah[i][3], bh[j][0], bh[j][1]);
#pragma unroll
            for (int i = 0; i < 2; i++)
#pragma unroll
                for (int j = 0; j < 4; j++)
                    mma_bf16(acc[i][j][0], acc[i][j][1], acc[i][j][2], acc[i][j][3],
                             al[i][0], al[i][1], al[i][2], al[i][3], bh[j][0], bh[j][1]);
#pragma unroll
            for (int i = 0; i < 2; i++)
#pragma unroll
                for (int j = 0; j < 4; j++)
                    mma_bf16(acc[i][j][0], acc[i][j][1], acc[i][j][2], acc[i][j][3],
                             ah[i][0], ah[i][1], ah[i][2], ah[i][3], bl[j][0], bl[j][1]);
        }
        if (k + 2 < NK) {
            int ns = s + 2; if (ns >= STAGES) ns -= STAGES;
            load_stage(k + 2, ns);
        }
        if (++s == STAGES) s = 0;
    }

    // ---- epilogue ----
    const int lrow = lane >> 2;          // 0..7
    const int lcol = (lane & 3) * 2;     // 0,2,4,6
#pragma unroll
    for (int i = 0; i < 2; i++) {
#pragma unroll
        for (int hh = 0; hh < 2; hh++) {
            const size_t row = (size_t)(brow + warp_m + i * 16 + lrow + hh * 8);
#pragma unroll
            for (int j = 0; j < 4; j++) {
                const size_t col = (size_t)(bcol + warp_n + j * 8 + lcol);
                float v0 = acc[i][j][2 * hh];
                float v1 = acc[i][j][2 * hh + 1];
                if (GELU_SPLIT) {
                    v0 = gelu_exact(v0);
                    v1 = gelu_exact(v1);
                    __nv_bfloat16 h0 = __float2bfloat16(v0);
                    __nv_bfloat16 h1 = __float2bfloat16(v1);
                    __nv_bfloat162 hp; hp.x = h0; hp.y = h1;
                    __nv_bfloat162 lp;
                    lp.x = __float2bfloat16(v0 - __bfloat162float(h0));
                    lp.y = __float2bfloat16(v1 - __bfloat162float(h1));
                    *reinterpret_cast<uint32_t*>(Ch + row * Ndim + col) =
                        *reinterpret_cast<uint32_t*>(&hp);
                    *reinterpret_cast<uint32_t*>(Cl + row * Ndim + col) =
                        *reinterpret_cast<uint32_t*>(&lp);
                } else {
                    float2 o; o.x = v0; o.y = v1;
                    *reinterpret_cast<float2*>(Cout + row * Ndim + col) = o;
                }
            }
        }
    }
}

// ======================= launch =======================
extern "C" void kernel_launch(void* const* d_in, const int* in_sizes, int n_in,
                              void* d_out, int out_size) {
    const float* x  = (const float*)d_in[0];
    const float* w1 = (const float*)d_in[1];
    const float* w2 = (const float*)d_in[2];
    float* out = (float*)d_out;
    (void)in_sizes; (void)n_in; (void)out_size;

    cudaFuncSetAttribute(hmma_gemm_kernel<true>,
                         cudaFuncAttributeMaxDynamicSharedMemorySize, SMEM_BYTES);
    cudaFuncSetAttribute(hmma_gemm_kernel<false>,
                         cudaFuncAttributeMaxDynamicSharedMemorySize, SMEM_BYTES);

    __nv_bfloat16 *xh, *xl, *w1h, *w1l, *w2h, *w2l, *hh, *hl;
    cudaGetSymbolAddress((void**)&xh,  g_xh);
    cudaGetSymbolAddress((void**)&xl,  g_xl);
    cudaGetSymbolAddress((void**)&w1h, g_w1h);
    cudaGetSymbolAddress((void**)&w1l, g_w1l);
    cudaGetSymbolAddress((void**)&w2h, g_w2h);
    cudaGetSymbolAddress((void**)&w2l, g_w2l);
    cudaGetSymbolAddress((void**)&hh,  g_hh);
    cudaGetSymbolAddress((void**)&hl,  g_hl);

    // 1) split x
    {
        size_t n4 = (size_t)E * M * D / 4;
        split_kernel<<<(unsigned)(n4 / 256), 256>>>((const float4*)x, xh, xl);
    }
    // 2) transpose+split w1: [E][D][H] -> [E][H][D]
    {
        dim3 grid(H / 32, D / 32, E), blk(32, 8);
        transpose_split_kernel<<<grid, blk>>>(w1, w1h, w1l, D, H);
    }
    // 3) transpose+split w2: [E][H][D] -> [E][D][H]
    {
        dim3 grid(D / 32, H / 32, E), blk(32, 8);
        transpose_split_kernel<<<grid, blk>>>(w2, w2h, w2l, H, D);
    }
    // 4) GEMM1 + GELU + split -> hidden planes  (M x H, K = D)
    {
        dim3 grid(H / 64, M / 128, E);
        hmma_gemm_kernel<true><<<grid, 256, SMEM_BYTES>>>(
            xh, xl, w1h, w1l, nullptr, hh, hl, M, H, D);
    }
    // 5) GEMM2 -> out  (M x D, K = H)
    {
        dim3 grid(D / 64, M / 128, E);
        hmma_gemm_kernel<false><<<grid, 256, SMEM_BYTES>>>(
            hh, hl, w2h, w2l, out, nullptr, nullptr, M, D, H);
    }
}